// round 1
// baseline (speedup 1.0000x reference)
#include <cuda_runtime.h>

// NetVLAD fused pool, fp32 SIMT, sm_103a.
// Shapes: BT=256 (m), N=2048, C=64, K=32. out[m][k][c] (256*32*64 fp32).
// Decomposition per CTA = (m, s): rows n in [s*512, s*512+512), tiles of 128.
//   Stage A: logits = Rtile(128x64) @ W^T(64x32) + b -> softmax rows -> An(128x32)
//   Stage B: V(32x64) += An^T @ Rtile ; asum += colsum(An)
//   Epilogue: atomicAdd(out, V - asum*centroid)  (out zeroed by nv_zero first)

namespace {
constexpr int BT    = 256;
constexpr int Nn    = 2048;
constexpr int Cc    = 64;
constexpr int Kk    = 32;
constexpr int SPLIT = 4;
constexpr int NT    = 128;
constexpr int TILES = (Nn / SPLIT) / NT;   // 4
constexpr int RP    = 68;                  // Rrow smem pitch (floats)
constexpr int AP    = 36;                  // An smem pitch (floats)
constexpr int SMEM_BYTES = (NT * RP + NT * AP + Cc * Kk) * 4; // 61440
}

__global__ void nv_zero(float4* __restrict__ out, int n4) {
    int i = blockIdx.x * blockDim.x + threadIdx.x;
    if (i < n4) out[i] = make_float4(0.f, 0.f, 0.f, 0.f);
}

__global__ __launch_bounds__(256) void nv_main(
    const float* __restrict__ R, const float* __restrict__ W,
    const float* __restrict__ bvec, const float* __restrict__ cent,
    float* __restrict__ out)
{
    extern __shared__ float sm[];
    float* Rrow = sm;                    // [NT][RP] row-major R tile
    float* An   = sm + NT * RP;          // [NT][AP] softmax probs
    float* Ws   = sm + NT * RP + NT * AP;// [C][K]   W transposed

    const int t = threadIdx.x;
    const int m = blockIdx.x >> 2;
    const int s = blockIdx.x & 3;

    // W (K,C) global -> Ws[c][k] in smem (coalesced read, once per CTA)
    #pragma unroll
    for (int i = 0; i < 8; i++) {
        int idx = i * 256 + t;               // idx = k*64 + c
        Ws[(idx & 63) * Kk + (idx >> 6)] = W[idx];
    }

    // ---- Stage A thread mapping: thread = (ng, kg); rows ng+32*i, k = 4*kg+j
    const int kg = t & 7;
    const int ng = t >> 3;
    const float4 bias = *reinterpret_cast<const float4*>(bvec + 4 * kg);

    // ---- Stage B thread mapping: half h over n, tile 4k x 4c
    const int h   = t >> 7;           // n-half
    const int kg2 = t & 7;            // k0 = 4*kg2
    const int cg  = (t >> 3) & 15;    // c0 = 4*cg

    float vB[4][4];
    float asum[4] = {0.f, 0.f, 0.f, 0.f};
    #pragma unroll
    for (int j = 0; j < 4; j++)
        #pragma unroll
        for (int q = 0; q < 4; q++) vB[j][q] = 0.f;

    const float* Rbase = R + ((size_t)m * Nn + (size_t)s * (Nn / SPLIT)) * Cc;

    for (int tile = 0; tile < TILES; ++tile) {
        __syncthreads();   // prior stage B done with Rrow/An

        // ---- Load R tile: 128x64 floats, coalesced float4
        const float4* Rg = reinterpret_cast<const float4*>(Rbase + (size_t)tile * NT * Cc);
        #pragma unroll
        for (int i = 0; i < 8; i++) {
            int idx = i * 256 + t;           // 0..2047 float4s
            float4 v = Rg[idx];
            *reinterpret_cast<float4*>(Rrow + (idx >> 4) * RP + (idx & 15) * 4) = v;
        }
        __syncthreads();

        // ---- Stage A: logits GEMM (4 rows x 4 k per thread)
        float acc[4][4];
        #pragma unroll
        for (int i = 0; i < 4; i++) {
            acc[i][0] = bias.x; acc[i][1] = bias.y;
            acc[i][2] = bias.z; acc[i][3] = bias.w;
        }
        #pragma unroll
        for (int c0 = 0; c0 < Cc; c0 += 4) {
            float4 w0 = *reinterpret_cast<const float4*>(Ws + (c0 + 0) * Kk + 4 * kg);
            float4 w1 = *reinterpret_cast<const float4*>(Ws + (c0 + 1) * Kk + 4 * kg);
            float4 w2 = *reinterpret_cast<const float4*>(Ws + (c0 + 2) * Kk + 4 * kg);
            float4 w3 = *reinterpret_cast<const float4*>(Ws + (c0 + 3) * Kk + 4 * kg);
            #pragma unroll
            for (int i = 0; i < 4; i++) {
                float4 r = *reinterpret_cast<const float4*>(Rrow + (ng + 32 * i) * RP + c0);
                acc[i][0] = fmaf(r.x, w0.x, acc[i][0]);
                acc[i][0] = fmaf(r.y, w1.x, acc[i][0]);
                acc[i][0] = fmaf(r.z, w2.x, acc[i][0]);
                acc[i][0] = fmaf(r.w, w3.x, acc[i][0]);
                acc[i][1] = fmaf(r.x, w0.y, acc[i][1]);
                acc[i][1] = fmaf(r.y, w1.y, acc[i][1]);
                acc[i][1] = fmaf(r.z, w2.y, acc[i][1]);
                acc[i][1] = fmaf(r.w, w3.y, acc[i][1]);
                acc[i][2] = fmaf(r.x, w0.z, acc[i][2]);
                acc[i][2] = fmaf(r.y, w1.z, acc[i][2]);
                acc[i][2] = fmaf(r.z, w2.z, acc[i][2]);
                acc[i][2] = fmaf(r.w, w3.z, acc[i][2]);
                acc[i][3] = fmaf(r.x, w0.w, acc[i][3]);
                acc[i][3] = fmaf(r.y, w1.w, acc[i][3]);
                acc[i][3] = fmaf(r.z, w2.w, acc[i][3]);
                acc[i][3] = fmaf(r.w, w3.w, acc[i][3]);
            }
        }

        // ---- Softmax per row across the 8 kg-lanes (bfly 1,2,4)
        #pragma unroll
        for (int i = 0; i < 4; i++) {
            float mx = fmaxf(fmaxf(acc[i][0], acc[i][1]), fmaxf(acc[i][2], acc[i][3]));
            mx = fmaxf(mx, __shfl_xor_sync(0xffffffffu, mx, 1));
            mx = fmaxf(mx, __shfl_xor_sync(0xffffffffu, mx, 2));
            mx = fmaxf(mx, __shfl_xor_sync(0xffffffffu, mx, 4));
            float e0 = __expf(acc[i][0] - mx);
            float e1 = __expf(acc[i][1] - mx);
            float e2 = __expf(acc[i][2] - mx);
            float e3 = __expf(acc[i][3] - mx);
            float ss = (e0 + e1) + (e2 + e3);
            ss += __shfl_xor_sync(0xffffffffu, ss, 1);
            ss += __shfl_xor_sync(0xffffffffu, ss, 2);
            ss += __shfl_xor_sync(0xffffffffu, ss, 4);
            float inv = __fdividef(1.f, ss);
            float4 a4 = make_float4(e0 * inv, e1 * inv, e2 * inv, e3 * inv);
            *reinterpret_cast<float4*>(An + (ng + 32 * i) * AP + 4 * kg) = a4;
        }
        __syncthreads();

        // ---- Stage B: V += A^T @ R over this tile (each half over 64 rows)
        const int nbase = h * (NT / 2);
        #pragma unroll 4
        for (int nn = 0; nn < NT / 2; ++nn) {
            int n = nbase + nn;
            float4 a4 = *reinterpret_cast<const float4*>(An + n * AP + 4 * kg2);
            float4 r4 = *reinterpret_cast<const float4*>(Rrow + n * RP + 4 * cg);
            vB[0][0] = fmaf(a4.x, r4.x, vB[0][0]);
            vB[0][1] = fmaf(a4.x, r4.y, vB[0][1]);
            vB[0][2] = fmaf(a4.x, r4.z, vB[0][2]);
            vB[0][3] = fmaf(a4.x, r4.w, vB[0][3]);
            vB[1][0] = fmaf(a4.y, r4.x, vB[1][0]);
            vB[1][1] = fmaf(a4.y, r4.y, vB[1][1]);
            vB[1][2] = fmaf(a4.y, r4.z, vB[1][2]);
            vB[1][3] = fmaf(a4.y, r4.w, vB[1][3]);
            vB[2][0] = fmaf(a4.z, r4.x, vB[2][0]);
            vB[2][1] = fmaf(a4.z, r4.y, vB[2][1]);
            vB[2][2] = fmaf(a4.z, r4.z, vB[2][2]);
            vB[2][3] = fmaf(a4.z, r4.w, vB[2][3]);
            vB[3][0] = fmaf(a4.w, r4.x, vB[3][0]);
            vB[3][1] = fmaf(a4.w, r4.y, vB[3][1]);
            vB[3][2] = fmaf(a4.w, r4.z, vB[3][2]);
            vB[3][3] = fmaf(a4.w, r4.w, vB[3][3]);
            asum[0] += a4.x; asum[1] += a4.y; asum[2] += a4.z; asum[3] += a4.w;
        }
    }

    // ---- Epilogue: fold -asum*centroid, reduce into out
    float* outm = out + (size_t)m * Kk * Cc;
    #pragma unroll
    for (int j = 0; j < 4; j++) {
        int k = 4 * kg2 + j;
        const float4 c4 = *reinterpret_cast<const float4*>(cent + k * Cc + 4 * cg);
        float* o = outm + k * Cc + 4 * cg;
        atomicAdd(o + 0, vB[j][0] - asum[j] * c4.x);
        atomicAdd(o + 1, vB[j][1] - asum[j] * c4.y);
        atomicAdd(o + 2, vB[j][2] - asum[j] * c4.z);
        atomicAdd(o + 3, vB[j][3] - asum[j] * c4.w);
    }
}

extern "C" void kernel_launch(void* const* d_in, const int* in_sizes, int n_in,
                              void* d_out, int out_size) {
    const float* R    = (const float*)d_in[0];
    const float* W    = (const float*)d_in[1];
    const float* b    = (const float*)d_in[2];
    const float* cent = (const float*)d_in[3];
    float* out = (float*)d_out;

    cudaFuncSetAttribute(nv_main, cudaFuncAttributeMaxDynamicSharedMemorySize, SMEM_BYTES);

    int n4 = out_size / 4;   // 131072 float4s
    nv_zero<<<(n4 + 255) / 256, 256>>>((float4*)out, n4);
    nv_main<<<BT * SPLIT, 256, SMEM_BYTES>>>(R, W, b, cent, out);
}